// round 7
// baseline (speedup 1.0000x reference)
#include <cuda_runtime.h>

#define N_BATCH 4
#define KCH 4
#define WS 64
#define PPTS 4096
#define QTILE 2S6   /* placeholder guard against typo; real def below */
#undef QTILE
#define QTILE 256          /* q tile points */
#define PSUPER 512         /* p supertile points (2 per thread) */
#define NQT (PPTS/QTILE)   /* 16 */
#define NST (PPTS/PSUPER)  /* 8 */
#define BLOCK 256
#define GRIDX (NST*NQT)    /* 128 cells; J<2S cells exit early */
#define TOTALB (GRIDX*N_BATCH)

__device__ double g_acc;          // zero-initialized; finalizer resets for graph replay
__device__ unsigned int g_done;

__device__ __forceinline__ float ex2f(float a) {
    float r; asm("ex2.approx.ftz.f32 %0, %1;" : "=f"(r) : "f"(a)); return r;
}

// Compute one point's record from raw inputs (img/sg pre-offset to batch n).
// f[10] = {fx,fy,fr,fg,fb,h,s0,s1,s2,s3}; features pre-scaled by sqrt(log2 e),
// h = -0.5*||f_scaled||^2 so exp(-0.5 d^2) == ex2(h_p + h_q + f_p.f_q).
__device__ __forceinline__ void compute_pt(const float* __restrict__ img,
                                           const float* __restrict__ sg,
                                           int p, float* f) {
    const float SQL2E = 1.2011224087864498f;   // sqrt(log2 e)
    int y = p >> 6, x = p & 63;
    int ro = (y << 8) + (x << 1);              // (2y)*128 + 2x
    float fx = (float)x * (SQL2E / 50.0f);     // SIGMA_XY*SCALE = 50
    float fy = (float)y * (SQL2E / 50.0f);
    float fr = img[ro]           * (SQL2E / 15.0f);
    float fg = img[16384 + ro]   * (SQL2E / 15.0f);
    float fb = img[32768 + ro]   * (SQL2E / 15.0f);
    float h  = -0.5f * (fx*fx + fy*fy + fr*fr + fg*fg + fb*fb);
    f[0]=fx; f[1]=fy; f[2]=fr; f[3]=fg; f[4]=fb; f[5]=h;
#pragma unroll
    for (int k = 0; k < KCH; k++) {
        const float* sk = sg + k * 16384;
        f[6+k] = (sk[ro] + sk[ro+1] + sk[ro+128] + sk[ro+129]) * 0.25f;
    }
}

__global__ void __launch_bounds__(BLOCK) crf_kernel(const float* __restrict__ images,
                                                    const float* __restrict__ segs,
                                                    float* __restrict__ out) {
    __shared__ float4 tile[QTILE * 3];   // 12 KB
    __shared__ float wsum[BLOCK / 32];

    int t = blockIdx.x;
    int n = blockIdx.y;
    int S = t >> 4;          // p supertile (512 points -> rows 2S, 2S+1)
    int J = t & 15;          // q tile (256 points)

    if (J >= 2 * S) {
        const float* img = images + (size_t)n * 3 * 16384;
        const float* sg  = segs   + (size_t)n * KCH * 16384;
        int tid = threadIdx.x;

        // q point -> shared
        {
            float q[10];
            compute_pt(img, sg, J * QTILE + tid, q);
            tile[tid*3 + 0] = make_float4(q[0], q[1], q[2], q[3]);
            tile[tid*3 + 1] = make_float4(q[4], q[5], q[6], q[7]);
            tile[tid*3 + 2] = make_float4(q[8], q[9], 0.0f, 0.0f);
        }

        // two p points -> registers
        float P0[10], P1[10];
        compute_pt(img, sg, S * PSUPER + tid, P0);
        compute_pt(img, sg, S * PSUPER + QTILE + tid, P1);

        __syncthreads();

        float a00=0.f, a01=0.f, a02=0.f, a03=0.f;
        float a10=0.f, a11=0.f, a12=0.f, a13=0.f;
#pragma unroll 4
        for (int j = 0; j < QTILE; j++) {
            float4 a = tile[j*3 + 0];
            float4 b = tile[j*3 + 1];
            float4 c = tile[j*3 + 2];

            float arg0 = P0[5] + b.y;
            arg0 = fmaf(P0[0], a.x, arg0);
            arg0 = fmaf(P0[1], a.y, arg0);
            arg0 = fmaf(P0[2], a.z, arg0);
            arg0 = fmaf(P0[3], a.w, arg0);
            arg0 = fmaf(P0[4], b.x, arg0);
            float arg1 = P1[5] + b.y;
            arg1 = fmaf(P1[0], a.x, arg1);
            arg1 = fmaf(P1[1], a.y, arg1);
            arg1 = fmaf(P1[2], a.z, arg1);
            arg1 = fmaf(P1[3], a.w, arg1);
            arg1 = fmaf(P1[4], b.x, arg1);

            float e0 = ex2f(arg0);
            float e1 = ex2f(arg1);

            a00 = fmaf(e0, b.z, a00);
            a01 = fmaf(e0, b.w, a01);
            a02 = fmaf(e0, c.x, a02);
            a03 = fmaf(e0, c.y, a03);
            a10 = fmaf(e1, b.z, a10);
            a11 = fmaf(e1, b.w, a11);
            a12 = fmaf(e1, c.x, a12);
            a13 = fmaf(e1, c.y, a13);
        }

        // row weights for the symmetric triangle
        float w0 = (J == 2*S) ? 1.0f : 2.0f;                       // row I0 = 2S (J>=2S)
        float w1 = (J == 2*S) ? 0.0f : ((J == 2*S+1) ? 1.0f : 2.0f); // row I1 = 2S+1

        float r0 = P0[6]*a00; r0 = fmaf(P0[7], a01, r0);
        r0 = fmaf(P0[8], a02, r0); r0 = fmaf(P0[9], a03, r0);
        float r1 = P1[6]*a10; r1 = fmaf(P1[7], a11, r1);
        r1 = fmaf(P1[8], a12, r1); r1 = fmaf(P1[9], a13, r1);
        float acc = fmaf(w0, r0, w1 * r1);

        // warp + block reduce, one double atomic per block
#pragma unroll
        for (int off = 16; off > 0; off >>= 1)
            acc += __shfl_down_sync(0xFFFFFFFFu, acc, off);
        int lane = tid & 31, warp = tid >> 5;
        if (lane == 0) wsum[warp] = acc;
        __syncthreads();
        if (tid == 0) {
            float s = 0.0f;
#pragma unroll
            for (int i = 0; i < BLOCK / 32; i++) s += wsum[i];
            atomicAdd(&g_acc, (double)s);
        }
    }

    // completion protocol (all blocks, including skipped ones)
    if (threadIdx.x == 0) {
        __threadfence();
        unsigned int d = atomicAdd(&g_done, 1u);
        if (d == TOTALB - 1u) {
            double total = *((volatile double*)&g_acc);
            out[0] = (float)(total * (-1e-7 / (double)N_BATCH));
            // reset for next graph replay
            g_acc = 0.0;
            g_done = 0u;
        }
    }
}

extern "C" void kernel_launch(void* const* d_in, const int* in_sizes, int n_in,
                              void* d_out, int out_size) {
    const float* images = (const float*)d_in[0];
    const float* segs   = (const float*)d_in[1];
    dim3 grid(GRIDX, N_BATCH);
    crf_kernel<<<grid, BLOCK>>>(images, segs, (float*)d_out);
}

// round 8
// speedup vs baseline: 1.6531x; 1.6531x over previous
#include <cuda_runtime.h>

#define N_BATCH 4
#define KCH 4
#define PPTS 4096
#define QTILE 256          /* q tile points */
#define PSUPER 512         /* p supertile points (2 per thread) */
#define NQT 16             /* PPTS/QTILE */
#define NST 8              /* PPTS/PSUPER */
#define BLOCK 256
#define CELLS 72           /* active (S,J) cells per batch: sum_{S=0}^{7}(16-2S) */
#define TOTALB (CELLS*N_BATCH)

__device__ double g_acc;          // zero-initialized; last block resets for graph replay
__device__ unsigned int g_done;

// prefix[S] = number of active cells before supertile S  (counts 16,14,12,10,8,6,4,2)
__constant__ int c_pre[9] = {0, 16, 30, 42, 52, 60, 66, 70, 72};

__device__ __forceinline__ float ex2f(float a) {
    float r; asm("ex2.approx.ftz.f32 %0, %1;" : "=f"(r) : "f"(a)); return r;
}

// f[10] = {fx,fy,fr,fg,fb,h,s0,s1,s2,s3}; features pre-scaled by sqrt(log2 e),
// h = -0.5*||f_scaled||^2 so exp(-0.5 d^2) == ex2(h_p + h_q + f_p.f_q).
__device__ __forceinline__ void compute_pt(const float* __restrict__ img,
                                           const float* __restrict__ sg,
                                           int p, float* f) {
    const float SQL2E = 1.2011224087864498f;   // sqrt(log2 e)
    int y = p >> 6, x = p & 63;
    int ro = (y << 8) + (x << 1);              // (2y)*128 + 2x
    float fx = (float)x * (SQL2E / 50.0f);     // SIGMA_XY*SCALE = 50
    float fy = (float)y * (SQL2E / 50.0f);
    float fr = img[ro]         * (SQL2E / 15.0f);
    float fg = img[16384 + ro] * (SQL2E / 15.0f);
    float fb = img[32768 + ro] * (SQL2E / 15.0f);
    float h  = -0.5f * (fx*fx + fy*fy + fr*fr + fg*fg + fb*fb);
    f[0]=fx; f[1]=fy; f[2]=fr; f[3]=fg; f[4]=fb; f[5]=h;
#pragma unroll
    for (int k = 0; k < KCH; k++) {
        const float* sk = sg + k * 16384;
        f[6+k] = (sk[ro] + sk[ro+1] + sk[ro+128] + sk[ro+129]) * 0.25f;
    }
}

__global__ void __launch_bounds__(BLOCK) crf_kernel(const float* __restrict__ images,
                                                    const float* __restrict__ segs,
                                                    float* __restrict__ out) {
    __shared__ float4 tA[QTILE];     // {fx,fy,fr,fg}
    __shared__ float4 tB[QTILE];     // {fb,h,s0,s1}
    __shared__ float2 tC[QTILE];     // {s2,s3}
    __shared__ float wsum[BLOCK / 32];

    // Decode compact cell index -> (S, J) with J >= 2S. All blocks do equal work.
    int t = blockIdx.x;
    int n = blockIdx.y;
    int S = 0;
#pragma unroll
    for (int s = 1; s < NST; s++)
        if (t >= c_pre[s]) S = s;
    int J = 2 * S + (t - c_pre[S]);

    const float* img = images + (size_t)n * 3 * 16384;
    const float* sg  = segs   + (size_t)n * KCH * 16384;
    int tid = threadIdx.x;

    // q point -> shared (SoA)
    {
        float q[10];
        compute_pt(img, sg, J * QTILE + tid, q);
        tA[tid] = make_float4(q[0], q[1], q[2], q[3]);
        tB[tid] = make_float4(q[4], q[5], q[6], q[7]);
        tC[tid] = make_float2(q[8], q[9]);
    }

    // two p points -> registers
    float P0[10], P1[10];
    compute_pt(img, sg, S * PSUPER + tid, P0);
    compute_pt(img, sg, S * PSUPER + QTILE + tid, P1);

    __syncthreads();

    float a00=0.f, a01=0.f, a02=0.f, a03=0.f;
    float a10=0.f, a11=0.f, a12=0.f, a13=0.f;
#pragma unroll 4
    for (int j = 0; j < QTILE; j++) {
        float4 a = tA[j];
        float4 b = tB[j];
        float2 c = tC[j];

        float arg0 = P0[5] + b.y;
        arg0 = fmaf(P0[0], a.x, arg0);
        arg0 = fmaf(P0[1], a.y, arg0);
        arg0 = fmaf(P0[2], a.z, arg0);
        arg0 = fmaf(P0[3], a.w, arg0);
        arg0 = fmaf(P0[4], b.x, arg0);
        float arg1 = P1[5] + b.y;
        arg1 = fmaf(P1[0], a.x, arg1);
        arg1 = fmaf(P1[1], a.y, arg1);
        arg1 = fmaf(P1[2], a.z, arg1);
        arg1 = fmaf(P1[3], a.w, arg1);
        arg1 = fmaf(P1[4], b.x, arg1);

        float e0 = ex2f(arg0);
        float e1 = ex2f(arg1);

        a00 = fmaf(e0, b.z, a00);
        a01 = fmaf(e0, b.w, a01);
        a02 = fmaf(e0, c.x, a02);
        a03 = fmaf(e0, c.y, a03);
        a10 = fmaf(e1, b.z, a10);
        a11 = fmaf(e1, b.w, a11);
        a12 = fmaf(e1, c.x, a12);
        a13 = fmaf(e1, c.y, a13);
    }

    // row weights for the symmetric triangle (rows 2S and 2S+1, column J >= 2S)
    float w0 = (J == 2*S) ? 1.0f : 2.0f;
    float w1 = (J == 2*S) ? 0.0f : ((J == 2*S + 1) ? 1.0f : 2.0f);

    float r0 = P0[6]*a00; r0 = fmaf(P0[7], a01, r0);
    r0 = fmaf(P0[8], a02, r0); r0 = fmaf(P0[9], a03, r0);
    float r1 = P1[6]*a10; r1 = fmaf(P1[7], a11, r1);
    r1 = fmaf(P1[8], a12, r1); r1 = fmaf(P1[9], a13, r1);
    float acc = fmaf(w0, r0, w1 * r1);

    // warp + block reduce, one double atomic per block
#pragma unroll
    for (int off = 16; off > 0; off >>= 1)
        acc += __shfl_down_sync(0xFFFFFFFFu, acc, off);
    int lane = tid & 31, warp = tid >> 5;
    if (lane == 0) wsum[warp] = acc;
    __syncthreads();
    if (tid == 0) {
        float s = 0.0f;
#pragma unroll
        for (int i = 0; i < BLOCK / 32; i++) s += wsum[i];
        atomicAdd(&g_acc, (double)s);
        __threadfence();
        unsigned int d = atomicAdd(&g_done, 1u);
        if (d == TOTALB - 1u) {
            double total = *((volatile double*)&g_acc);
            out[0] = (float)(total * (-1e-7 / (double)N_BATCH));
            g_acc = 0.0;      // reset for next graph replay
            g_done = 0u;
        }
    }
}

extern "C" void kernel_launch(void* const* d_in, const int* in_sizes, int n_in,
                              void* d_out, int out_size) {
    const float* images = (const float*)d_in[0];
    const float* segs   = (const float*)d_in[1];
    dim3 grid(CELLS, N_BATCH);
    crf_kernel<<<grid, BLOCK>>>(images, segs, (float*)d_out);
}